// round 3
// baseline (speedup 1.0000x reference)
#include <cuda_runtime.h>
#include <cstdint>

// ---------------------------------------------------------------------------
// microGIF step, N=8192.
//   K1: eps[j] = (1+tanh(t))*exp(-t/tau_s)/tau_s  (fast math; sets g_flag)
//   K2 (fused): if g_flag==0 -> per-thread update with I_syn = 0
//               else         -> per-row 128-thread dot + lane-0 update
//   Bernoulli: JAX threefry2x32 partitionable, key=(0,42), bits = x0^x1.
// Outputs concatenated: [0:N) lambda, [N:2N) spiked_new, [2N:3N) v_new
// ---------------------------------------------------------------------------

#define NMAX 8192

__device__ float g_eps[NMAX];
__device__ int   g_flag;   // 1 if any eps != 0

// ---------------- K1: eps + flag, single block, fast math ------------------
__global__ void k_eps(const float* __restrict__ tss,
                      const float* __restrict__ tau_s, int n) {
    __shared__ int s_any;
    if (threadIdx.x == 0) s_any = 0;
    __syncthreads();
    int local = 0;
    for (int i = threadIdx.x; i < n; i += blockDim.x) {
        float t = tss[i] - 1.0f;                    // DELTA_DELAY = 1.0
        float ts = tau_s[i];
        // tanh(t) = 1 - 2/(e^{2t}+1); exact +/-1 saturation at large |t|,
        // and __expf(-t/ts) underflows to exactly 0 like libm expf.
        float e2t = __expf(2.0f * t);
        float th  = 1.0f - 2.0f / (e2t + 1.0f);
        float e   = (1.0f + th) * __expf(-t / ts) / ts;
        g_eps[i] = e;
        if (e != 0.0f) local = 1;
    }
    if (__syncthreads_or(local)) { if (threadIdx.x == 0) g_flag = 1; }
    else                         { if (threadIdx.x == 0) g_flag = 0; }
}

// ---------------- JAX threefry2x32, partitionable counter mode -------------
__device__ __forceinline__ uint32_t rotl32(uint32_t x, int r) {
    return (x << r) | (x >> (32 - r));
}

__device__ __forceinline__ uint32_t jax_bits_partitionable(uint32_t i) {
    const uint32_t k0 = 0u, k1 = 42u;
    const uint32_t k2 = k0 ^ k1 ^ 0x1BD11BDAu;
    uint32_t ks[3] = {k0, k1, k2};
    uint32_t x0 = k0;        // counter hi word = 0
    uint32_t x1 = i + k1;    // counter lo word = i
    const int rot[8] = {13, 15, 26, 6, 17, 29, 16, 24};
    #pragma unroll
    for (int it = 0; it < 5; it++) {
        const int* rr = rot + 4 * (it & 1);
        #pragma unroll
        for (int j = 0; j < 4; j++) {
            x0 += x1;
            x1 = rotl32(x1, rr[j]);
            x1 ^= x0;
        }
        x0 += ks[(it + 1) % 3];
        x1 += ks[(it + 2) % 3] + (uint32_t)(it + 1);
    }
    return x0 ^ x1;
}

// ---------------- per-neuron scalar update ---------------------------------
__device__ __forceinline__ void neuron_update(
    int i, int n, float Isyn,
    const float* __restrict__ I_ext, const float* __restrict__ v,
    const float* __restrict__ spiked, const float* __restrict__ tss,
    const float* __restrict__ theta_v, const float* __restrict__ tau_m,
    const float* __restrict__ tau_theta, const float* __restrict__ J_theta,
    const float* __restrict__ E_L, const float* __restrict__ c,
    const float* __restrict__ Delta_u, const float* __restrict__ theta_inf,
    float* __restrict__ out) {
    float th = theta_v[i] +
               (theta_inf[i] - theta_v[i] + J_theta[i] * spiked[i]) / tau_theta[i];
    float vi = v[i];
    float v_next = vi + (E_L[i] - vi + I_ext[i]) / tau_m[i] + Isyn;

    float notref = (tss[i] > 2.0f) ? 1.0f : 0.0f;   // T_REFRACTORY = 2.0
    float lam = notref * c[i] * expf((v_next - th) / Delta_u[i]);
    lam = fminf(fmaxf(lam, 0.0f), 1.0f);

    uint32_t bits = jax_bits_partitionable((uint32_t)i);
    float u = __uint_as_float((bits >> 9) | 0x3F800000u) - 1.0f;
    float sp = (u < lam) ? 1.0f : 0.0f;
    float v_new = (sp != 0.0f) ? 0.0f : v_next;     // RESET_POTENTIAL = 0

    out[i]         = lam;
    out[n + i]     = sp;
    out[2 * n + i] = v_new;
}

// ---------------- K2: fused matvec + update --------------------------------
__global__ void k_fused(const float* __restrict__ w,
                        const float* __restrict__ I_ext,
                        const float* __restrict__ v,
                        const float* __restrict__ spiked,
                        const float* __restrict__ tss,
                        const float* __restrict__ theta_v,
                        const float* __restrict__ tau_m,
                        const float* __restrict__ tau_theta,
                        const float* __restrict__ J_theta,
                        const float* __restrict__ E_L,
                        const float* __restrict__ c,
                        const float* __restrict__ Delta_u,
                        const float* __restrict__ theta_inf,
                        float* __restrict__ out, int n) {
    int flag = g_flag;                      // broadcast load, same addr
    if (flag == 0) {
        // eps == 0 everywhere -> I_syn == 0 (incl. diagonal term).
        // First ceil(n/128) blocks do one neuron per thread; rest exit.
        int i = blockIdx.x * blockDim.x + threadIdx.x;
        if (i < n)
            neuron_update(i, n, 0.0f, I_ext, v, spiked, tss, theta_v, tau_m,
                          tau_theta, J_theta, E_L, c, Delta_u, theta_inf, out);
        return;
    }

    // General path: one block per row.
    int row = blockIdx.x;
    const float4* __restrict__ wr =
        reinterpret_cast<const float4*>(w + (size_t)row * n);
    const float4* __restrict__ ev = reinterpret_cast<const float4*>(g_eps);
    float s = 0.0f;
    int nq = n >> 2;
    for (int k = threadIdx.x; k < nq; k += blockDim.x) {
        float4 a = wr[k];
        float4 b = ev[k];
        s += a.x * b.x + a.y * b.y + a.z * b.z + a.w * b.w;
    }
    #pragma unroll
    for (int o = 16; o > 0; o >>= 1) s += __shfl_down_sync(0xffffffffu, s, o);
    __shared__ float ws[4];
    if ((threadIdx.x & 31) == 0) ws[threadIdx.x >> 5] = s;
    __syncthreads();
    if (threadIdx.x == 0) {
        float t = ws[0] + ws[1] + ws[2] + ws[3];
        float Isyn = t - w[(size_t)row * n + row] * g_eps[row];
        neuron_update(row, n, Isyn, I_ext, v, spiked, tss, theta_v, tau_m,
                      tau_theta, J_theta, E_L, c, Delta_u, theta_inf, out);
    }
}

extern "C" void kernel_launch(void* const* d_in, const int* in_sizes, int n_in,
                              void* d_out, int out_size) {
    const float* I_ext     = (const float*)d_in[0];
    const float* w         = (const float*)d_in[1];
    const float* v         = (const float*)d_in[2];
    const float* spiked    = (const float*)d_in[3];
    const float* tss       = (const float*)d_in[4];
    const float* theta_v   = (const float*)d_in[5];
    const float* tau_m     = (const float*)d_in[6];
    const float* tau_s     = (const float*)d_in[7];
    const float* tau_theta = (const float*)d_in[8];
    const float* J_theta   = (const float*)d_in[9];
    const float* E_L       = (const float*)d_in[10];
    const float* c         = (const float*)d_in[11];
    const float* Delta_u   = (const float*)d_in[12];
    const float* theta_inf = (const float*)d_in[13];
    float* out = (float*)d_out;

    int n = in_sizes[0];
    if (n > NMAX) n = NMAX;

    k_eps<<<1, 1024>>>(tss, tau_s, n);
    k_fused<<<n, 128>>>(w, I_ext, v, spiked, tss, theta_v, tau_m, tau_theta,
                        J_theta, E_L, c, Delta_u, theta_inf, out, n);
}

// round 6
// speedup vs baseline: 1.3375x; 1.3375x over previous
#include <cuda_runtime.h>
#include <cstdint>

// ---------------------------------------------------------------------------
// microGIF step, N=8192 — two kernels (proven-running skeleton).
//   K1 <<<1,1024>>> : eps[j] = (1+tanh(t))*exp(-t/tau_s)/tau_s (fast math),
//                     sets g_flag = any(eps != 0).
//   K2 <<<256,256>>>: if g_flag==0 -> first 32 blocks: one neuron/thread,
//                     I_syn = 0. else -> blocks stride rows, 256-thread dot
//                     of W row against g_eps (L2-resident), then update.
// Bernoulli: JAX threefry2x32 partitionable, key=(0,42), bits = x0 ^ x1.
// Outputs: [0:N) lambda, [N:2N) spiked_new, [2N:3N) v_new
// ---------------------------------------------------------------------------

#define NMAX 8192
#define GRID 256
#define BLK  256

__device__ float g_eps[NMAX];
__device__ int   g_flag;   // 1 if any eps != 0

// ---------------- K1: eps + flag, single block, fast math ------------------
__global__ void k_eps(const float* __restrict__ tss,
                      const float* __restrict__ tau_s, int n) {
    int any = 0;
    for (int i = threadIdx.x; i < n; i += blockDim.x) {
        float t = tss[i] - 1.0f;                    // DELTA_DELAY = 1.0
        float ts = tau_s[i];
        // tanh(t) = 1 - 2/(e^{2t}+1): exact +/-1 saturation at large |t|;
        // __expf(-t/ts) underflows to exactly 0 like libm expf.
        float e2t = __expf(2.0f * t);
        float thv = 1.0f - 2.0f / (e2t + 1.0f);
        float e   = (1.0f + thv) * __expf(-t / ts) / ts;
        g_eps[i] = e;
        any |= (e != 0.0f);
    }
    int flag = __syncthreads_or(any);
    if (threadIdx.x == 0) g_flag = flag ? 1 : 0;
}

// ---------------- JAX threefry2x32, partitionable counter mode -------------
__device__ __forceinline__ uint32_t rotl32(uint32_t x, int r) {
    return (x << r) | (x >> (32 - r));
}

__device__ __forceinline__ uint32_t jax_bits_partitionable(uint32_t i) {
    const uint32_t k0 = 0u, k1 = 42u;
    const uint32_t k2 = k0 ^ k1 ^ 0x1BD11BDAu;
    uint32_t ks[3] = {k0, k1, k2};
    uint32_t x0 = k0;        // counter hi word = 0
    uint32_t x1 = i + k1;    // counter lo word = i
    const int rot[8] = {13, 15, 26, 6, 17, 29, 16, 24};
    #pragma unroll
    for (int it = 0; it < 5; it++) {
        const int* rr = rot + 4 * (it & 1);
        #pragma unroll
        for (int j = 0; j < 4; j++) {
            x0 += x1;
            x1 = rotl32(x1, rr[j]);
            x1 ^= x0;
        }
        x0 += ks[(it + 1) % 3];
        x1 += ks[(it + 2) % 3] + (uint32_t)(it + 1);
    }
    return x0 ^ x1;
}

// ---------------- per-neuron scalar update ---------------------------------
__device__ __forceinline__ void neuron_update(
    int i, int n, float Isyn,
    const float* __restrict__ I_ext, const float* __restrict__ v,
    const float* __restrict__ spiked, const float* __restrict__ tss,
    const float* __restrict__ theta_v, const float* __restrict__ tau_m,
    const float* __restrict__ tau_theta, const float* __restrict__ J_theta,
    const float* __restrict__ E_L, const float* __restrict__ c,
    const float* __restrict__ Delta_u, const float* __restrict__ theta_inf,
    float* __restrict__ out) {
    float th = theta_v[i] +
               (theta_inf[i] - theta_v[i] + J_theta[i] * spiked[i]) / tau_theta[i];
    float vi = v[i];
    float v_next = vi + (E_L[i] - vi + I_ext[i]) / tau_m[i] + Isyn;

    float notref = (tss[i] > 2.0f) ? 1.0f : 0.0f;   // T_REFRACTORY = 2.0
    float lam = notref * c[i] * expf((v_next - th) / Delta_u[i]);  // accurate
    lam = fminf(fmaxf(lam, 0.0f), 1.0f);

    uint32_t bits = jax_bits_partitionable((uint32_t)i);
    float u = __uint_as_float((bits >> 9) | 0x3F800000u) - 1.0f;
    float sp = (u < lam) ? 1.0f : 0.0f;
    float v_new = (sp != 0.0f) ? 0.0f : v_next;     // RESET_POTENTIAL = 0

    out[i]         = lam;
    out[n + i]     = sp;
    out[2 * n + i] = v_new;
}

// ---------------- K2: fused matvec + update, grid = 256 --------------------
__global__ __launch_bounds__(BLK)
void k_fused(const float* __restrict__ w,
             const float* __restrict__ I_ext,
             const float* __restrict__ v,
             const float* __restrict__ spiked,
             const float* __restrict__ tss,
             const float* __restrict__ theta_v,
             const float* __restrict__ tau_m,
             const float* __restrict__ tau_theta,
             const float* __restrict__ J_theta,
             const float* __restrict__ E_L,
             const float* __restrict__ c,
             const float* __restrict__ Delta_u,
             const float* __restrict__ theta_inf,
             float* __restrict__ out, int n) {
    int tid = threadIdx.x;
    if (g_flag == 0) {
        // eps == 0 everywhere -> I_syn == 0 exactly (incl. diagonal term).
        int i = blockIdx.x * BLK + tid;
        if (i < n)
            neuron_update(i, n, 0.0f, I_ext, v, spiked, tss, theta_v, tau_m,
                          tau_theta, J_theta, E_L, c, Delta_u, theta_inf, out);
        return;
    }

    // General path: blocks stride rows; eps stays L2-resident.
    __shared__ float ws[BLK / 32];
    for (int row = blockIdx.x; row < n; row += GRID) {
        const float4* __restrict__ wr =
            reinterpret_cast<const float4*>(w + (size_t)row * n);
        const float4* __restrict__ ev =
            reinterpret_cast<const float4*>(g_eps);
        float s = 0.0f;
        int nq = n >> 2;
        for (int k = tid; k < nq; k += BLK) {
            float4 a = wr[k];
            float4 b = ev[k];
            s += a.x * b.x + a.y * b.y + a.z * b.z + a.w * b.w;
        }
        #pragma unroll
        for (int o = 16; o > 0; o >>= 1)
            s += __shfl_down_sync(0xffffffffu, s, o);
        if ((tid & 31) == 0) ws[tid >> 5] = s;
        __syncthreads();
        if (tid == 0) {
            float t = 0.0f;
            #pragma unroll
            for (int j = 0; j < BLK / 32; j++) t += ws[j];
            float Isyn = t - w[(size_t)row * n + row] * g_eps[row];
            neuron_update(row, n, Isyn, I_ext, v, spiked, tss, theta_v, tau_m,
                          tau_theta, J_theta, E_L, c, Delta_u, theta_inf, out);
        }
        __syncthreads();
    }
}

extern "C" void kernel_launch(void* const* d_in, const int* in_sizes, int n_in,
                              void* d_out, int out_size) {
    const float* I_ext     = (const float*)d_in[0];
    const float* w         = (const float*)d_in[1];
    const float* v         = (const float*)d_in[2];
    const float* spiked    = (const float*)d_in[3];
    const float* tss       = (const float*)d_in[4];
    const float* theta_v   = (const float*)d_in[5];
    const float* tau_m     = (const float*)d_in[6];
    const float* tau_s     = (const float*)d_in[7];
    const float* tau_theta = (const float*)d_in[8];
    const float* J_theta   = (const float*)d_in[9];
    const float* E_L       = (const float*)d_in[10];
    const float* c         = (const float*)d_in[11];
    const float* Delta_u   = (const float*)d_in[12];
    const float* theta_inf = (const float*)d_in[13];
    float* out = (float*)d_out;

    int n = in_sizes[0];
    if (n > NMAX) n = NMAX;

    k_eps<<<1, 1024>>>(tss, tau_s, n);
    k_fused<<<GRID, BLK>>>(w, I_ext, v, spiked, tss, theta_v, tau_m,
                           tau_theta, J_theta, E_L, c, Delta_u, theta_inf,
                           out, n);
}

// round 7
// speedup vs baseline: 1.9669x; 1.4706x over previous
#include <cuda_runtime.h>
#include <cstdint>

// ---------------------------------------------------------------------------
// microGIF step, N=8192 — two kernels.
//   K1 <<<32,256>>> : eps[i] = (1+tanh(t))*exp(-t/tau_s)/tau_s (fast math),
//                     one element/thread; per-block flag -> g_bflag[32].
//   K2 <<<256,256>>>: OR the 32 flag words; if all-zero -> first 32 blocks do
//                     one neuron/thread with I_syn = 0; else blocks stride
//                     rows, 256-thread dot of W row vs g_eps, then update.
// Bernoulli: JAX threefry2x32 partitionable, key=(0,42), bits = x0 ^ x1.
// Outputs: [0:N) lambda, [N:2N) spiked_new, [2N:3N) v_new
// ---------------------------------------------------------------------------

#define NMAX     8192
#define GRID     256
#define BLK      256
#define EPSBLKS  32

__device__ float    g_eps[NMAX];
__device__ unsigned g_bflag[EPSBLKS];   // per-block "any eps != 0"

// ---------------- K1: eps + per-block flag, fast math ----------------------
__global__ __launch_bounds__(BLK)
void k_eps(const float* __restrict__ tss,
           const float* __restrict__ tau_s, int n) {
    int any = 0;
    for (int i = blockIdx.x * BLK + threadIdx.x; i < n; i += EPSBLKS * BLK) {
        float t = tss[i] - 1.0f;                    // DELTA_DELAY = 1.0
        float ts = tau_s[i];
        // tanh(t) = 1 - 2/(e^{2t}+1): exact +/-1 saturation at large |t|;
        // __expf(-t/ts) underflows to exactly 0 like libm expf.
        float e2t = __expf(2.0f * t);
        float thv = 1.0f - 2.0f / (e2t + 1.0f);
        float e   = (1.0f + thv) * __expf(-t / ts) / ts;
        g_eps[i] = e;
        any |= (e != 0.0f);
    }
    int flag = __syncthreads_or(any);
    if (threadIdx.x == 0) g_bflag[blockIdx.x] = flag ? 1u : 0u;
}

// ---------------- JAX threefry2x32, partitionable counter mode -------------
__device__ __forceinline__ uint32_t rotl32(uint32_t x, int r) {
    return (x << r) | (x >> (32 - r));
}

__device__ __forceinline__ uint32_t jax_bits_partitionable(uint32_t i) {
    const uint32_t k0 = 0u, k1 = 42u;
    const uint32_t k2 = k0 ^ k1 ^ 0x1BD11BDAu;
    uint32_t ks[3] = {k0, k1, k2};
    uint32_t x0 = k0;        // counter hi word = 0
    uint32_t x1 = i + k1;    // counter lo word = i
    const int rot[8] = {13, 15, 26, 6, 17, 29, 16, 24};
    #pragma unroll
    for (int it = 0; it < 5; it++) {
        const int* rr = rot + 4 * (it & 1);
        #pragma unroll
        for (int j = 0; j < 4; j++) {
            x0 += x1;
            x1 = rotl32(x1, rr[j]);
            x1 ^= x0;
        }
        x0 += ks[(it + 1) % 3];
        x1 += ks[(it + 2) % 3] + (uint32_t)(it + 1);
    }
    return x0 ^ x1;
}

// ---------------- per-neuron scalar update ---------------------------------
__device__ __forceinline__ void neuron_update(
    int i, int n, float Isyn,
    const float* __restrict__ I_ext, const float* __restrict__ v,
    const float* __restrict__ spiked, const float* __restrict__ tss,
    const float* __restrict__ theta_v, const float* __restrict__ tau_m,
    const float* __restrict__ tau_theta, const float* __restrict__ J_theta,
    const float* __restrict__ E_L, const float* __restrict__ c,
    const float* __restrict__ Delta_u, const float* __restrict__ theta_inf,
    float* __restrict__ out) {
    float th = theta_v[i] +
               (theta_inf[i] - theta_v[i] + J_theta[i] * spiked[i]) / tau_theta[i];
    float vi = v[i];
    float v_next = vi + (E_L[i] - vi + I_ext[i]) / tau_m[i] + Isyn;

    float notref = (tss[i] > 2.0f) ? 1.0f : 0.0f;   // T_REFRACTORY = 2.0
    float lam = notref * c[i] * __expf((v_next - th) / Delta_u[i]);
    lam = fminf(fmaxf(lam, 0.0f), 1.0f);

    uint32_t bits = jax_bits_partitionable((uint32_t)i);
    float u = __uint_as_float((bits >> 9) | 0x3F800000u) - 1.0f;
    float sp = (u < lam) ? 1.0f : 0.0f;
    float v_new = (sp != 0.0f) ? 0.0f : v_next;     // RESET_POTENTIAL = 0

    out[i]         = lam;
    out[n + i]     = sp;
    out[2 * n + i] = v_new;
}

// ---------------- K2: fused matvec + update, grid = 256 --------------------
__global__ __launch_bounds__(BLK)
void k_fused(const float* __restrict__ w,
             const float* __restrict__ I_ext,
             const float* __restrict__ v,
             const float* __restrict__ spiked,
             const float* __restrict__ tss,
             const float* __restrict__ theta_v,
             const float* __restrict__ tau_m,
             const float* __restrict__ tau_theta,
             const float* __restrict__ J_theta,
             const float* __restrict__ E_L,
             const float* __restrict__ c,
             const float* __restrict__ Delta_u,
             const float* __restrict__ theta_inf,
             float* __restrict__ out, int n) {
    int tid = threadIdx.x;
    unsigned f = (tid < EPSBLKS) ? g_bflag[tid] : 0u;
    int flag = __syncthreads_or(f != 0u);

    if (flag == 0) {
        // eps == 0 everywhere -> I_syn == 0 exactly (incl. diagonal term).
        int i = blockIdx.x * BLK + tid;
        if (i < n)
            neuron_update(i, n, 0.0f, I_ext, v, spiked, tss, theta_v, tau_m,
                          tau_theta, J_theta, E_L, c, Delta_u, theta_inf, out);
        return;
    }

    // General path: blocks stride rows; eps stays L2-resident.
    __shared__ float ws[BLK / 32];
    for (int row = blockIdx.x; row < n; row += GRID) {
        const float4* __restrict__ wr =
            reinterpret_cast<const float4*>(w + (size_t)row * n);
        const float4* __restrict__ ev =
            reinterpret_cast<const float4*>(g_eps);
        float s = 0.0f;
        int nq = n >> 2;
        for (int k = tid; k < nq; k += BLK) {
            float4 a = wr[k];
            float4 b = ev[k];
            s += a.x * b.x + a.y * b.y + a.z * b.z + a.w * b.w;
        }
        #pragma unroll
        for (int o = 16; o > 0; o >>= 1)
            s += __shfl_down_sync(0xffffffffu, s, o);
        if ((tid & 31) == 0) ws[tid >> 5] = s;
        __syncthreads();
        if (tid == 0) {
            float t = 0.0f;
            #pragma unroll
            for (int j = 0; j < BLK / 32; j++) t += ws[j];
            float Isyn = t - w[(size_t)row * n + row] * g_eps[row];
            neuron_update(row, n, Isyn, I_ext, v, spiked, tss, theta_v, tau_m,
                          tau_theta, J_theta, E_L, c, Delta_u, theta_inf, out);
        }
        __syncthreads();
    }
}

extern "C" void kernel_launch(void* const* d_in, const int* in_sizes, int n_in,
                              void* d_out, int out_size) {
    const float* I_ext     = (const float*)d_in[0];
    const float* w         = (const float*)d_in[1];
    const float* v         = (const float*)d_in[2];
    const float* spiked    = (const float*)d_in[3];
    const float* tss       = (const float*)d_in[4];
    const float* theta_v   = (const float*)d_in[5];
    const float* tau_m     = (const float*)d_in[6];
    const float* tau_s     = (const float*)d_in[7];
    const float* tau_theta = (const float*)d_in[8];
    const float* J_theta   = (const float*)d_in[9];
    const float* E_L       = (const float*)d_in[10];
    const float* c         = (const float*)d_in[11];
    const float* Delta_u   = (const float*)d_in[12];
    const float* theta_inf = (const float*)d_in[13];
    float* out = (float*)d_out;

    int n = in_sizes[0];
    if (n > NMAX) n = NMAX;

    k_eps<<<EPSBLKS, BLK>>>(tss, tau_s, n);
    k_fused<<<GRID, BLK>>>(w, I_ext, v, spiked, tss, theta_v, tau_m,
                           tau_theta, J_theta, E_L, c, Delta_u, theta_inf,
                           out, n);
}

// round 9
// speedup vs baseline: 2.2574x; 1.1477x over previous
#include <cuda_runtime.h>
#include <cstdint>

// ---------------------------------------------------------------------------
// microGIF step, N=8192 — SINGLE kernel, grid = 32 x 256, NO inter-block sync.
//
// Each block independently screens all (tss, tau_s) pairs:
//   e = (1+tanh(t))*exp(-t/ts)/ts is GUARANTEED == 0 in fp32 when
//   t > 110*ts && ts > 0  (exp underflows past denormal range; tanh finite).
//   Screen is conservative: NaN / ts<=0 / t<=110*ts  => "maybe nonzero".
// All blocks compute the same screen -> same branch, deterministically.
//   screen all-zero : I_syn == 0 exactly -> one neuron/thread update.
//   maybe nonzero   : block builds full eps in ITS OWN smem (fast math),
//                     then strides rows: 256-thread dot of W row vs smem eps.
//                     (A false-positive screen still yields Isyn == 0 exactly.)
// Bernoulli: JAX threefry2x32 partitionable, key=(0,42), bits = x0 ^ x1.
// Outputs: [0:N) lambda, [N:2N) spiked_new, [2N:3N) v_new
// ---------------------------------------------------------------------------

#define NMAX  8192
#define BLK   256

// ---------------- JAX threefry2x32, partitionable counter mode -------------
__device__ __forceinline__ uint32_t rotl32(uint32_t x, int r) {
    return (x << r) | (x >> (32 - r));
}

__device__ __forceinline__ uint32_t jax_bits_partitionable(uint32_t i) {
    const uint32_t k0 = 0u, k1 = 42u;
    const uint32_t k2 = k0 ^ k1 ^ 0x1BD11BDAu;
    uint32_t ks[3] = {k0, k1, k2};
    uint32_t x0 = k0;        // counter hi word = 0
    uint32_t x1 = i + k1;    // counter lo word = i
    const int rot[8] = {13, 15, 26, 6, 17, 29, 16, 24};
    #pragma unroll
    for (int it = 0; it < 5; it++) {
        const int* rr = rot + 4 * (it & 1);
        #pragma unroll
        for (int j = 0; j < 4; j++) {
            x0 += x1;
            x1 = rotl32(x1, rr[j]);
            x1 ^= x0;
        }
        x0 += ks[(it + 1) % 3];
        x1 += ks[(it + 2) % 3] + (uint32_t)(it + 1);
    }
    return x0 ^ x1;
}

// ---------------- per-neuron scalar update ---------------------------------
__device__ __forceinline__ void neuron_update(
    int i, int n, float Isyn,
    const float* __restrict__ I_ext, const float* __restrict__ v,
    const float* __restrict__ spiked, const float* __restrict__ tss,
    const float* __restrict__ theta_v, const float* __restrict__ tau_m,
    const float* __restrict__ tau_theta, const float* __restrict__ J_theta,
    const float* __restrict__ E_L, const float* __restrict__ c,
    const float* __restrict__ Delta_u, const float* __restrict__ theta_inf,
    float* __restrict__ out) {
    float th = theta_v[i] +
               (theta_inf[i] - theta_v[i] + J_theta[i] * spiked[i]) / tau_theta[i];
    float vi = v[i];
    float v_next = vi + (E_L[i] - vi + I_ext[i]) / tau_m[i] + Isyn;

    float notref = (tss[i] > 2.0f) ? 1.0f : 0.0f;   // T_REFRACTORY = 2.0
    float lam = notref * c[i] * __expf((v_next - th) / Delta_u[i]);
    lam = fminf(fmaxf(lam, 0.0f), 1.0f);

    uint32_t bits = jax_bits_partitionable((uint32_t)i);
    float u = __uint_as_float((bits >> 9) | 0x3F800000u) - 1.0f;
    float sp = (u < lam) ? 1.0f : 0.0f;
    float v_new = (sp != 0.0f) ? 0.0f : v_next;     // RESET_POTENTIAL = 0

    out[i]         = lam;
    out[n + i]     = sp;
    out[2 * n + i] = v_new;
}

// "e might be nonzero" — conservative (true on NaN, ts<=0, or no underflow).
__device__ __forceinline__ bool maybe_nz(float tssv, float ts) {
    float t = tssv - 1.0f;                          // DELTA_DELAY = 1.0
    return !((t > 110.0f * ts) && (ts > 0.0f));
}

// ---------------- the single kernel ----------------------------------------
__global__ __launch_bounds__(BLK)
void k_gif(const float* __restrict__ w,
           const float* __restrict__ I_ext,
           const float* __restrict__ v,
           const float* __restrict__ spiked,
           const float* __restrict__ tss,
           const float* __restrict__ tau_s,
           const float* __restrict__ theta_v,
           const float* __restrict__ tau_m,
           const float* __restrict__ tau_theta,
           const float* __restrict__ J_theta,
           const float* __restrict__ E_L,
           const float* __restrict__ c,
           const float* __restrict__ Delta_u,
           const float* __restrict__ theta_inf,
           float* __restrict__ out, int n) {
    const int tid = threadIdx.x;

    // ---- conservative zero screen over ALL n elements (every block) ----
    int any = 0;
    int nq = n >> 2;                    // n is a multiple of 4 here (8192)
    const float4* __restrict__ t4p = reinterpret_cast<const float4*>(tss);
    const float4* __restrict__ s4p = reinterpret_cast<const float4*>(tau_s);
    for (int k = tid; k < nq; k += BLK) {
        float4 t4 = t4p[k];
        float4 s4 = s4p[k];
        any |= maybe_nz(t4.x, s4.x) | maybe_nz(t4.y, s4.y) |
               maybe_nz(t4.z, s4.z) | maybe_nz(t4.w, s4.w);
    }
    for (int k = (nq << 2) + tid; k < n; k += BLK)   // tail (none for 8192)
        any |= maybe_nz(tss[k], tau_s[k]);
    int flag = __syncthreads_or(any);

    if (flag == 0) {
        // every eps underflows to exactly 0 -> I_syn == 0 exactly.
        int i = blockIdx.x * BLK + tid;
        if (i < n)
            neuron_update(i, n, 0.0f, I_ext, v, spiked, tss, theta_v, tau_m,
                          tau_theta, J_theta, E_L, c, Delta_u, theta_inf, out);
        return;
    }

    // ---- general path: block-local eps in smem, then strided rows ----
    __shared__ float s_eps[NMAX];
    __shared__ float ws[BLK / 32];
    for (int i = tid; i < n; i += BLK) {
        float t  = tss[i] - 1.0f;
        float ts = tau_s[i];
        // tanh(t) = 1 - 2/(e^{2t}+1): exact +/-1 saturation; __expf
        // underflows to exactly 0 like libm expf.
        float e2t = __expf(2.0f * t);
        float thv = 1.0f - 2.0f / (e2t + 1.0f);
        s_eps[i] = (1.0f + thv) * __expf(-t / ts) / ts;
    }
    __syncthreads();

    for (int row = blockIdx.x; row < n; row += gridDim.x) {
        const float4* __restrict__ wr =
            reinterpret_cast<const float4*>(w + (size_t)row * n);
        const float4* __restrict__ ev =
            reinterpret_cast<const float4*>(s_eps);
        float s = 0.0f;
        for (int k = tid; k < nq; k += BLK) {
            float4 a = wr[k];
            float4 b = ev[k];
            s += a.x * b.x + a.y * b.y + a.z * b.z + a.w * b.w;
        }
        #pragma unroll
        for (int o = 16; o > 0; o >>= 1)
            s += __shfl_down_sync(0xffffffffu, s, o);
        if ((tid & 31) == 0) ws[tid >> 5] = s;
        __syncthreads();
        if (tid == 0) {
            float t = 0.0f;
            #pragma unroll
            for (int j = 0; j < BLK / 32; j++) t += ws[j];
            float Isyn = t - w[(size_t)row * n + row] * s_eps[row];
            neuron_update(row, n, Isyn, I_ext, v, spiked, tss, theta_v, tau_m,
                          tau_theta, J_theta, E_L, c, Delta_u, theta_inf, out);
        }
        __syncthreads();
    }
}

extern "C" void kernel_launch(void* const* d_in, const int* in_sizes, int n_in,
                              void* d_out, int out_size) {
    const float* I_ext     = (const float*)d_in[0];
    const float* w         = (const float*)d_in[1];
    const float* v         = (const float*)d_in[2];
    const float* spiked    = (const float*)d_in[3];
    const float* tss       = (const float*)d_in[4];
    const float* theta_v   = (const float*)d_in[5];
    const float* tau_m     = (const float*)d_in[6];
    const float* tau_s     = (const float*)d_in[7];
    const float* tau_theta = (const float*)d_in[8];
    const float* J_theta   = (const float*)d_in[9];
    const float* E_L       = (const float*)d_in[10];
    const float* c         = (const float*)d_in[11];
    const float* Delta_u   = (const float*)d_in[12];
    const float* theta_inf = (const float*)d_in[13];
    float* out = (float*)d_out;

    int n = in_sizes[0];
    if (n > NMAX) n = NMAX;

    int nb = (n + BLK - 1) / BLK;          // 32 blocks for n = 8192
    k_gif<<<nb, BLK>>>(w, I_ext, v, spiked, tss, tau_s, theta_v, tau_m,
                       tau_theta, J_theta, E_L, c, Delta_u, theta_inf,
                       out, n);
}

// round 10
// speedup vs baseline: 2.5971x; 1.1505x over previous
#include <cuda_runtime.h>
#include <cstdint>

// ---------------------------------------------------------------------------
// microGIF step, N=8192 — SINGLE kernel, grid = 8 x 1024, NO inter-block sync.
//
// Each block independently screens all (tss, tau_s) pairs:
//   e = (1+tanh(t))*exp(-t/ts)/ts is GUARANTEED == 0 in fp32 when
//   t > 110*ts && ts > 0 (exp underflows past denormals; tanh finite).
//   Conservative: NaN / ts<=0 / t<=110*ts => "maybe nonzero".
// The per-neuron update inputs + threefry bits are computed BEFORE the
// screen barrier (independent of the flag) to hide L2 latency.
//   screen all-zero : I_syn == 0 exactly -> finish update from registers.
//   maybe nonzero   : block builds full eps in its own smem (fast math),
//                     strides rows: 1024-thread dot of W row vs smem eps.
// Bernoulli: JAX threefry2x32 partitionable, key=(0,42), bits = x0 ^ x1.
// Outputs: [0:N) lambda, [N:2N) spiked_new, [2N:3N) v_new
// ---------------------------------------------------------------------------

#define NMAX  8192
#define BLK   1024

// ---------------- JAX threefry2x32, partitionable counter mode -------------
__device__ __forceinline__ uint32_t rotl32(uint32_t x, int r) {
    return (x << r) | (x >> (32 - r));
}

__device__ __forceinline__ uint32_t jax_bits_partitionable(uint32_t i) {
    const uint32_t k0 = 0u, k1 = 42u;
    const uint32_t k2 = k0 ^ k1 ^ 0x1BD11BDAu;
    uint32_t ks[3] = {k0, k1, k2};
    uint32_t x0 = k0;        // counter hi word = 0
    uint32_t x1 = i + k1;    // counter lo word = i
    const int rot[8] = {13, 15, 26, 6, 17, 29, 16, 24};
    #pragma unroll
    for (int it = 0; it < 5; it++) {
        const int* rr = rot + 4 * (it & 1);
        #pragma unroll
        for (int j = 0; j < 4; j++) {
            x0 += x1;
            x1 = rotl32(x1, rr[j]);
            x1 ^= x0;
        }
        x0 += ks[(it + 1) % 3];
        x1 += ks[(it + 2) % 3] + (uint32_t)(it + 1);
    }
    return x0 ^ x1;
}

// ---------------- per-neuron update from preloaded registers ---------------
__device__ __forceinline__ void update_store(
    int i, int n, float Isyn,
    float xI, float xv, float xs, float xtss, float xth, float xtm,
    float xtt, float xJ, float xE, float xc, float xD, float xti,
    uint32_t bits, float* __restrict__ out) {
    float th = xth + (xti - xth + xJ * xs) / xtt;
    float v_next = xv + (xE - xv + xI) / xtm + Isyn;

    float notref = (xtss > 2.0f) ? 1.0f : 0.0f;     // T_REFRACTORY = 2.0
    float lam = notref * xc * __expf((v_next - th) / xD);
    lam = fminf(fmaxf(lam, 0.0f), 1.0f);

    float u = __uint_as_float((bits >> 9) | 0x3F800000u) - 1.0f;
    float sp = (u < lam) ? 1.0f : 0.0f;
    float v_new = (sp != 0.0f) ? 0.0f : v_next;     // RESET_POTENTIAL = 0

    out[i]         = lam;
    out[n + i]     = sp;
    out[2 * n + i] = v_new;
}

// "e might be nonzero" — conservative (true on NaN, ts<=0, or no underflow).
__device__ __forceinline__ int maybe_nz(float tssv, float ts) {
    float t = tssv - 1.0f;                          // DELTA_DELAY = 1.0
    return !((t > 110.0f * ts) && (ts > 0.0f));
}

// ---------------- the single kernel ----------------------------------------
__global__ __launch_bounds__(BLK)
void k_gif(const float* __restrict__ w,
           const float* __restrict__ I_ext,
           const float* __restrict__ v,
           const float* __restrict__ spiked,
           const float* __restrict__ tss,
           const float* __restrict__ tau_s,
           const float* __restrict__ theta_v,
           const float* __restrict__ tau_m,
           const float* __restrict__ tau_theta,
           const float* __restrict__ J_theta,
           const float* __restrict__ E_L,
           const float* __restrict__ c,
           const float* __restrict__ Delta_u,
           const float* __restrict__ theta_inf,
           float* __restrict__ out, int n) {
    const int tid = threadIdx.x;
    const int i   = blockIdx.x * BLK + tid;
    const int nq  = n >> 2;

    // ---- conservative zero screen over ALL n elements (every block) ----
    int any = 0;
    const float4* __restrict__ t4p = reinterpret_cast<const float4*>(tss);
    const float4* __restrict__ s4p = reinterpret_cast<const float4*>(tau_s);
    #pragma unroll 2
    for (int k = tid; k < nq; k += BLK) {
        float4 t4 = t4p[k];
        float4 s4 = s4p[k];
        any |= maybe_nz(t4.x, s4.x) | maybe_nz(t4.y, s4.y) |
               maybe_nz(t4.z, s4.z) | maybe_nz(t4.w, s4.w);
    }
    for (int k = (nq << 2) + tid; k < n; k += BLK)   // tail (none for 8192)
        any |= maybe_nz(tss[k], tau_s[k]);

    // ---- preload update inputs + threefry BEFORE the barrier ----
    // (independent of the screen result; hides L2 latency behind ALU)
    float xI = 0, xv = 0, xs = 0, xtss = 0, xth = 0, xtm = 1,
          xtt = 1, xJ = 0, xE = 0, xc = 0, xD = 1, xti = 0;
    uint32_t bits = jax_bits_partitionable((uint32_t)i);
    if (i < n) {
        xI   = I_ext[i];    xv  = v[i];        xs  = spiked[i];
        xtss = tss[i];      xth = theta_v[i];  xtm = tau_m[i];
        xtt  = tau_theta[i];xJ  = J_theta[i];  xE  = E_L[i];
        xc   = c[i];        xD  = Delta_u[i];  xti = theta_inf[i];
    }

    int flag = __syncthreads_or(any);

    if (flag == 0) {
        // every eps underflows to exactly 0 -> I_syn == 0 exactly.
        if (i < n)
            update_store(i, n, 0.0f, xI, xv, xs, xtss, xth, xtm,
                         xtt, xJ, xE, xc, xD, xti, bits, out);
        return;
    }

    // ---- general path: block-local eps in smem, then strided rows ----
    __shared__ float s_eps[NMAX];
    __shared__ float ws[BLK / 32];
    for (int k = tid; k < n; k += BLK) {
        float t  = tss[k] - 1.0f;
        float ts = tau_s[k];
        // tanh(t) = 1 - 2/(e^{2t}+1): exact +/-1 saturation; __expf
        // underflows to exactly 0 like libm expf.
        float e2t = __expf(2.0f * t);
        float thv = 1.0f - 2.0f / (e2t + 1.0f);
        s_eps[k] = (1.0f + thv) * __expf(-t / ts) / ts;
    }
    __syncthreads();

    for (int row = blockIdx.x; row < n; row += gridDim.x) {
        const float4* __restrict__ wr =
            reinterpret_cast<const float4*>(w + (size_t)row * n);
        const float4* __restrict__ ev =
            reinterpret_cast<const float4*>(s_eps);
        float s = 0.0f;
        for (int k = tid; k < nq; k += BLK) {
            float4 a = wr[k];
            float4 b = ev[k];
            s += a.x * b.x + a.y * b.y + a.z * b.z + a.w * b.w;
        }
        #pragma unroll
        for (int o = 16; o > 0; o >>= 1)
            s += __shfl_down_sync(0xffffffffu, s, o);
        if ((tid & 31) == 0) ws[tid >> 5] = s;
        __syncthreads();
        if (tid == 0) {
            float t = 0.0f;
            #pragma unroll
            for (int j = 0; j < BLK / 32; j++) t += ws[j];
            float Isyn = t - w[(size_t)row * n + row] * s_eps[row];
            // reload this row's scalars (general path is not perf-critical)
            update_store(row, n, Isyn, I_ext[row], v[row], spiked[row],
                         tss[row], theta_v[row], tau_m[row], tau_theta[row],
                         J_theta[row], E_L[row], c[row], Delta_u[row],
                         theta_inf[row],
                         jax_bits_partitionable((uint32_t)row), out);
        }
        __syncthreads();
    }
}

extern "C" void kernel_launch(void* const* d_in, const int* in_sizes, int n_in,
                              void* d_out, int out_size) {
    const float* I_ext     = (const float*)d_in[0];
    const float* w         = (const float*)d_in[1];
    const float* v         = (const float*)d_in[2];
    const float* spiked    = (const float*)d_in[3];
    const float* tss       = (const float*)d_in[4];
    const float* theta_v   = (const float*)d_in[5];
    const float* tau_m     = (const float*)d_in[6];
    const float* tau_s     = (const float*)d_in[7];
    const float* tau_theta = (const float*)d_in[8];
    const float* J_theta   = (const float*)d_in[9];
    const float* E_L       = (const float*)d_in[10];
    const float* c         = (const float*)d_in[11];
    const float* Delta_u   = (const float*)d_in[12];
    const float* theta_inf = (const float*)d_in[13];
    float* out = (float*)d_out;

    int n = in_sizes[0];
    if (n > NMAX) n = NMAX;

    int nb = (n + BLK - 1) / BLK;          // 8 blocks for n = 8192
    k_gif<<<nb, BLK>>>(w, I_ext, v, spiked, tss, tau_s, theta_v, tau_m,
                       tau_theta, J_theta, E_L, c, Delta_u, theta_inf,
                       out, n);
}